// round 15
// baseline (speedup 1.0000x reference)
#include <cuda_runtime.h>
#include <cuda_bf16.h>
#include <cstdint>
#include <math.h>

#define BATCH 512
#define HID   1024
#define GATES 4096
#define TILEM 128          // batch rows per CTA
#define NH    32           // hidden units per CTA (-> 128 gate cols, gate-interleaved)
#define KC    64           // K chunk (bf16 elems), 128B rows
#define NCHUNK (HID / KC)  // 16
#define NPERS  8           // B chunks resident in SMEM
#define NTHREADS 512       // 16 warps, warp tile 32x32
#define GRP_CTAS 32        // CTAs per mb group

// ---- shared memory layout (bytes) ----
#define SO_X      0         // 128 f32
#define SO_WOUT   512       // 32 f32
#define SO_PRED   640       // 4*128 f32 -> ends 2688
#define SO_BPERS  3072      // 1024-aligned; 8 x 16384 = 131072 -> ends 134144
#define SO_STAGE  134144    // 1024-aligned; 3 stages x 32768
#define STAGE_BYTES 32768   // A(16KB) + streamed B(16KB)
#define TO_A      0
#define TO_B      16384
#define SMEM_TOTAL (SO_STAGE + 3 * STAGE_BYTES)   // 232448 == 227 KB cap

// ---------------- device scratch ----------------
__device__ __align__(128) __nv_bfloat16  g_hh  [2][BATCH * HID];   // double-buffered h (bf16)
__device__ __align__(128) __nv_bfloat16  g_Whi [GATES * HID];
__device__ __align__(128) float          g_parts[2][32 * BATCH];   // double-buffered readout partials
__device__ __align__(128) unsigned       g_bar[4];                 // per-mb-group barrier

// ---------------- helpers ----------------
__device__ __forceinline__ uint32_t smem_u32(const void* p) {
    uint32_t a;
    asm("{ .reg .u64 t; cvta.to.shared.u64 t, %1; cvt.u32.u64 %0, t; }" : "=r"(a) : "l"(p));
    return a;
}
__device__ __forceinline__ void cp16(uint32_t dst, const void* src) {
    asm volatile("cp.async.cg.shared.global [%0], [%1], 16;"
                 :: "r"(dst), "l"(__cvta_generic_to_global(src)));
}
__device__ __forceinline__ uint32_t swz(uint32_t off) { return off ^ ((off >> 3) & 0x70); }

__device__ __forceinline__ void ldsm4(uint32_t* r, uint32_t a) {
    asm volatile("ldmatrix.sync.aligned.m8n8.x4.shared.b16 {%0,%1,%2,%3}, [%4];"
                 : "=r"(r[0]), "=r"(r[1]), "=r"(r[2]), "=r"(r[3]) : "r"(a));
}
__device__ __forceinline__ void hmma(float* c, const uint32_t* a, const uint32_t* b) {
    asm volatile("mma.sync.aligned.m16n8k16.row.col.f32.bf16.bf16.f32 "
                 "{%0,%1,%2,%3}, {%4,%5,%6,%7}, {%8,%9}, {%0,%1,%2,%3};"
                 : "+f"(c[0]), "+f"(c[1]), "+f"(c[2]), "+f"(c[3])
                 : "r"(a[0]), "r"(a[1]), "r"(a[2]), "r"(a[3]), "r"(b[0]), "r"(b[1]));
}
__device__ __forceinline__ float sigf(float x) {
    return __fdividef(1.0f, 1.0f + __expf(-x));
}
__device__ __forceinline__ float tanhf_fast(float x) {
    float ax = fabsf(x);
    float e  = __expf(-2.0f * ax);
    float t  = __fdividef(1.0f - e, 1.0f + e);
    return copysignf(t, x);
}

// ---------------- prep / init ----------------
__global__ void prep_split_kernel(const float* __restrict__ W) {
    int n = GATES * HID;
    for (int i = blockIdx.x * blockDim.x + threadIdx.x; i < n; i += gridDim.x * blockDim.x) {
        g_Whi[i] = __float2bfloat16(W[i]);
    }
}
__global__ void init_zero_kernel() {
    int n = BATCH * HID;
    __nv_bfloat16 z = __float2bfloat16(0.0f);
    for (int i = blockIdx.x * blockDim.x + threadIdx.x; i < n; i += gridDim.x * blockDim.x) {
        g_hh[0][i] = z; g_hh[1][i] = z;
    }
    if (blockIdx.x == 0 && threadIdx.x < 4) g_bar[threadIdx.x] = 0u;
}

// ---------------- persistent LSTM kernel ----------------
__global__ void __launch_bounds__(NTHREADS, 1)
lstm_persist(const float* __restrict__ data, const float* __restrict__ W_ih,
             const float* __restrict__ b_ih, const float* __restrict__ b_hh,
             const float* __restrict__ W_out, const float* __restrict__ b_out,
             float* __restrict__ out, int T, int steps)
{
    extern __shared__ __align__(1024) char sm[];
    const uint32_t sb = smem_u32(sm);
    const int tid  = threadIdx.x;
    const int wid  = tid >> 5;
    const int lane = tid & 31;
    const int mb = blockIdx.x & 3;
    const int jb = blockIdx.x >> 2;
    const int m0 = mb * TILEM;
    const int j0 = jb * NH;
    const int wM = wid & 3;        // 0..3 -> 32-row slab
    const int wN = wid >> 2;       // 0..3 -> 32-col slab (8 hidden units x 4 gates)

    float* s_x    = (float*)(sm + SO_X);
    float* s_wout = (float*)(sm + SO_WOUT);
    float* s_pred = (float*)(sm + SO_PRED);

    // ---- one-time: per-thread gate weights/biases + wout, c state in regs ----
    const int hloc = wN * 8 + 2 * (lane & 3);
    float wih_r[4][2], bsum_r[4][2];
#pragma unroll
    for (int gt = 0; gt < 4; ++gt)
#pragma unroll
        for (int ej = 0; ej < 2; ++ej) {
            int j = gt * HID + j0 + hloc + ej;
            wih_r[gt][ej]  = W_ih[j];
            bsum_r[gt][ej] = b_ih[j] + b_hh[j];
        }
    if (tid < 32) s_wout[tid] = W_out[j0 + tid];
    const float bout = b_out[0];
    float c_reg[2][2][2];
#pragma unroll
    for (int a = 0; a < 2; ++a)
#pragma unroll
        for (int b = 0; b < 2; ++b)
#pragma unroll
            for (int d = 0; d < 2; ++d) c_reg[a][b][d] = 0.0f;

    const uint32_t aU = (uint32_t)((wM * 32 + (lane & 15)) * 128 + ((lane >> 4) * 8) * 2);
    const uint32_t bU = (uint32_t)((wN * 32 + (lane & 7) + ((lane >> 4) << 3)) * 128
                                   + (((lane >> 3) & 1) * 8) * 2);
    const uint32_t stg0 = sb + SO_STAGE;
    const uint32_t bpers = sb + SO_BPERS;

    // ---- B loader: gate-interleaved row r -> W row gate=(r>>3)&3, hid=(r&7)+((r>>5)<<3) ----
    auto load_B_to = [&](int chunk, uint32_t dstbase) {
        const int k0 = chunk * KC;
#pragma unroll
        for (int it = 0; it < 2; ++it) {
            int li = it * NTHREADS + tid;
            int r = li >> 3, c16 = li & 7;
            uint32_t soff = swz((uint32_t)(r * 128 + c16 * 16));
            int wrow = ((r >> 3) & 3) * HID + j0 + (r & 7) + ((r >> 5) << 3);
            size_t boff = (size_t)wrow * HID + k0 + c16 * 8;
            cp16(dstbase + soff, g_Whi + boff);
        }
    };
    auto load_A = [&](const __nv_bfloat16* hsrc, int chunk, uint32_t stg) {
        const int k0 = chunk * KC;
#pragma unroll
        for (int it = 0; it < 2; ++it) {
            int li = it * NTHREADS + tid;
            int r = li >> 3, c16 = li & 7;
            uint32_t soff = swz((uint32_t)(r * 128 + c16 * 16));
            size_t aoff = (size_t)(m0 + r) * HID + k0 + c16 * 8;
            cp16(stg + TO_A + soff, hsrc + aoff);
        }
    };

    // ---- one-time: persistent B chunks 0..NPERS-1 into SMEM ----
#pragma unroll 1
    for (int c = 0; c < NPERS; ++c)
        load_B_to(c, bpers + c * 16384);
    asm volatile("cp.async.commit_group;");
    asm volatile("cp.async.wait_group 0;");
    __syncthreads();

    const int total = T + steps - 1;   // 159 cell steps
    unsigned bar_target = 0;

    for (int g = 0; g < total; ++g) {
        const int rbuf = (g & 1) ^ 1;
        const int wbuf = g & 1;
        const __nv_bfloat16* hsrc = g_hh[rbuf];

        // ---- prime A chunks 0..1 (B for these is persistent) ----
        load_A(hsrc, 0, stg0 + 0 * STAGE_BYTES); asm volatile("cp.async.commit_group;");
        load_A(hsrc, 1, stg0 + 1 * STAGE_BYTES); asm volatile("cp.async.commit_group;");

        // ---- per-step prologue: x into SMEM (+ out write for AR steps) ----
        if (tid < 128) {
            float xv;
            if (g < T) {
                xv = data[(size_t)(m0 + tid) * T + g];
            } else {
                float acc2 = 0.0f;
#pragma unroll 8
                for (int p = 0; p < 32; ++p)
                    acc2 += __ldcg(&g_parts[rbuf][p * BATCH + m0 + tid]);
                xv = acc2 + bout;
                if (jb == 0) out[(size_t)(m0 + tid) * steps + (g - T)] = xv;
            }
            s_x[tid] = xv;
        }

        float acc[2][4][4];
#pragma unroll
        for (int mt = 0; mt < 2; ++mt)
#pragma unroll
            for (int nt = 0; nt < 4; ++nt)
#pragma unroll
                for (int e = 0; e < 4; ++e) acc[mt][nt][e] = 0.0f;

#pragma unroll 1
        for (int i = 0; i < NCHUNK; ++i) {
            if (i < NCHUNK - 1) asm volatile("cp.async.wait_group 1;");
            else                asm volatile("cp.async.wait_group 0;");
            __syncthreads();
            {
                const uint32_t stgA = stg0 + (i % 3) * STAGE_BYTES + TO_A;
                const uint32_t stgB = (i < NPERS) ? (bpers + i * 16384)
                                                  : (stg0 + (i % 3) * STAGE_BYTES + TO_B);
#pragma unroll
                for (int k16 = 0; k16 < 4; ++k16) {
                    const uint32_t ko = (uint32_t)k16 * 32;
                    uint32_t aHi[2][4];
#pragma unroll
                    for (int mt = 0; mt < 2; ++mt) {
                        uint32_t so = swz(aU + (uint32_t)mt * 2048 + ko);
                        ldsm4(aHi[mt], stgA + so);
                    }
                    uint32_t bH[4][2];
#pragma unroll
                    for (int half = 0; half < 2; ++half) {
                        uint32_t so = swz(bU + (uint32_t)half * 2048 + ko);
                        uint32_t t[4];
                        ldsm4(t, stgB + so);
                        bH[half*2][0] = t[0]; bH[half*2][1] = t[1];
                        bH[half*2+1][0] = t[2]; bH[half*2+1][1] = t[3];
                    }
#pragma unroll
                    for (int mt = 0; mt < 2; ++mt)
#pragma unroll
                        for (int nt = 0; nt < 4; ++nt)
                            hmma(acc[mt][nt], aHi[mt], bH[nt]);
                }
            }
            if (i + 2 < NCHUNK) {
                uint32_t stg = stg0 + ((i + 2) % 3) * STAGE_BYTES;
                load_A(hsrc, i + 2, stg);
                if (i + 2 >= NPERS) load_B_to(i + 2, stg + TO_B);
                asm volatile("cp.async.commit_group;");
            }
        }

        // ---- epilogue: register-resident cell update ----
        const float w0 = s_wout[hloc], w1 = s_wout[hloc + 1];
        const int hb = j0 + hloc;
#pragma unroll
        for (int mt = 0; mt < 2; ++mt)
#pragma unroll
            for (int eh = 0; eh < 2; ++eh) {
                const int rl = wM * 32 + mt * 16 + (lane >> 2) + eh * 8;
                const float xv = s_x[rl];
                float hn[2];
#pragma unroll
                for (int ej = 0; ej < 2; ++ej) {
                    const int e = eh * 2 + ej;
                    float gi = acc[mt][0][e] + xv * wih_r[0][ej] + bsum_r[0][ej];
                    float gf = acc[mt][1][e] + xv * wih_r[1][ej] + bsum_r[1][ej];
                    float gg = acc[mt][2][e] + xv * wih_r[2][ej] + bsum_r[2][ej];
                    float go = acc[mt][3][e] + xv * wih_r[3][ej] + bsum_r[3][ej];
                    float co = c_reg[mt][eh][ej];
                    float cn = sigf(gf) * co + sigf(gi) * tanhf_fast(gg);
                    hn[ej] = sigf(go) * tanhf_fast(cn);
                    c_reg[mt][eh][ej] = cn;
                }
                __nv_bfloat162 hv = __floats2bfloat162_rn(hn[0], hn[1]);
                *(uint32_t*)&g_hh[wbuf][(size_t)(m0 + rl) * HID + hb] =
                    *(uint32_t*)&hv;
                float p = hn[0] * w0 + hn[1] * w1;
                p += __shfl_xor_sync(0xFFFFFFFFu, p, 1);
                p += __shfl_xor_sync(0xFFFFFFFFu, p, 2);
                if ((lane & 3) == 0) s_pred[wN * 128 + rl] = p;
            }
        __syncthreads();
        if (tid < 128) {
            float p = s_pred[tid] + s_pred[128 + tid] + s_pred[256 + tid] + s_pred[384 + tid];
            g_parts[wbuf][jb * BATCH + m0 + tid] = p;
        }

        // ---- per-mb-group barrier (32 CTAs) ----
        bar_target += GRP_CTAS;
        __threadfence();
        __syncthreads();
        if (tid == 0) {
            atomicAdd(&g_bar[mb], 1u);
            while (*((volatile unsigned*)&g_bar[mb]) < bar_target) { __nanosleep(32); }
        }
        __syncthreads();
    }

    // ---- final prediction ----
    if (jb == 0 && tid < 128) {
        const int lbuf = (total - 1) & 1;
        float acc2 = 0.0f;
#pragma unroll 8
        for (int p = 0; p < 32; ++p)
            acc2 += __ldcg(&g_parts[lbuf][p * BATCH + m0 + tid]);
        out[(size_t)(m0 + tid) * steps + (steps - 1)] = acc2 + bout;
    }
}

// ---------------- launch ----------------
extern "C" void kernel_launch(void* const* d_in, const int* in_sizes, int n_in,
                              void* d_out, int out_size) {
    const float* data  = (const float*)d_in[0];  // [B, T, 1]
    const float* W_ih  = (const float*)d_in[1];  // [4H, 1]
    const float* W_hh  = (const float*)d_in[2];  // [4H, H]
    const float* b_ih  = (const float*)d_in[3];
    const float* b_hh  = (const float*)d_in[4];
    const float* W_out = (const float*)d_in[5];  // [1, H]
    const float* b_out = (const float*)d_in[6];
    float* out = (float*)d_out;                  // [B, STEPS, 1]

    int T     = in_sizes[0] / BATCH;   // 64
    int steps = out_size / BATCH;      // 96

    cudaFuncSetAttribute(lstm_persist, cudaFuncAttributeMaxDynamicSharedMemorySize, SMEM_TOTAL);

    prep_split_kernel<<<2048, 512>>>(W_hh);
    init_zero_kernel<<<512, 512>>>();

    lstm_persist<<<128, NTHREADS, SMEM_TOTAL>>>(data, W_ih, b_ih, b_hh,
                                                W_out, b_out, out, T, steps);
}

// round 16
// speedup vs baseline: 1.1020x; 1.1020x over previous
#include <cuda_runtime.h>
#include <cuda_bf16.h>
#include <cstdint>
#include <math.h>

#define BATCH 512
#define HID   1024
#define GATES 4096
#define TILEM 128          // batch rows per CTA
#define NH    32           // hidden units per CTA (-> 128 gate cols, gate-interleaved)
#define KC    128          // K chunk (bf16 elems) = 2 subtiles of 64
#define NCHUNK (HID / KC)  // 8
#define NTHREADS 512       // 16 warps, warp tile 32x32
#define GRP_CTAS 32        // CTAs per mb group

// ---- shared memory layout (bytes) ----
#define SO_X      0         // 128 f32
#define SO_WOUT   512       // 32 f32
#define SO_PRED   640       // 4*128 f32
#define SO_STAGE  4096      // 1024-aligned
#define STAGE_BYTES 65536   // A(32KB: 2 subtiles) + B(32KB)
#define TO_A      0
#define TO_B      32768
#define SMEM_TOTAL (SO_STAGE + 3 * STAGE_BYTES)   // 200704

// ---------------- device scratch ----------------
__device__ __align__(128) __nv_bfloat16  g_hh  [2][BATCH * HID];   // double-buffered h (bf16)
__device__ __align__(128) __nv_bfloat16  g_Whi [GATES * HID];
__device__ __align__(128) float          g_parts[2][32 * BATCH];   // double-buffered readout partials
__device__ __align__(128) unsigned       g_bar[4];                 // per-mb-group barrier

// ---------------- helpers ----------------
__device__ __forceinline__ uint32_t smem_u32(const void* p) {
    uint32_t a;
    asm("{ .reg .u64 t; cvta.to.shared.u64 t, %1; cvt.u32.u64 %0, t; }" : "=r"(a) : "l"(p));
    return a;
}
__device__ __forceinline__ void cp16(uint32_t dst, const void* src) {
    asm volatile("cp.async.cg.shared.global [%0], [%1], 16;"
                 :: "r"(dst), "l"(__cvta_generic_to_global(src)));
}
__device__ __forceinline__ uint32_t swz(uint32_t off) { return off ^ ((off >> 3) & 0x70); }

__device__ __forceinline__ void ldsm4(uint32_t* r, uint32_t a) {
    asm volatile("ldmatrix.sync.aligned.m8n8.x4.shared.b16 {%0,%1,%2,%3}, [%4];"
                 : "=r"(r[0]), "=r"(r[1]), "=r"(r[2]), "=r"(r[3]) : "r"(a));
}
__device__ __forceinline__ void hmma(float* c, const uint32_t* a, const uint32_t* b) {
    asm volatile("mma.sync.aligned.m16n8k16.row.col.f32.bf16.bf16.f32 "
                 "{%0,%1,%2,%3}, {%4,%5,%6,%7}, {%8,%9}, {%0,%1,%2,%3};"
                 : "+f"(c[0]), "+f"(c[1]), "+f"(c[2]), "+f"(c[3])
                 : "r"(a[0]), "r"(a[1]), "r"(a[2]), "r"(a[3]), "r"(b[0]), "r"(b[1]));
}
__device__ __forceinline__ float sigf(float x) {
    return __fdividef(1.0f, 1.0f + __expf(-x));
}
__device__ __forceinline__ float tanhf_fast(float x) {
    float ax = fabsf(x);
    float e  = __expf(-2.0f * ax);
    float t  = __fdividef(1.0f - e, 1.0f + e);
    return copysignf(t, x);
}

// ---------------- prep / init ----------------
__global__ void prep_split_kernel(const float* __restrict__ W) {
    int n = GATES * HID;
    for (int i = blockIdx.x * blockDim.x + threadIdx.x; i < n; i += gridDim.x * blockDim.x) {
        g_Whi[i] = __float2bfloat16(W[i]);
    }
}
__global__ void init_zero_kernel() {
    int n = BATCH * HID;
    __nv_bfloat16 z = __float2bfloat16(0.0f);
    for (int i = blockIdx.x * blockDim.x + threadIdx.x; i < n; i += gridDim.x * blockDim.x) {
        g_hh[0][i] = z; g_hh[1][i] = z;
    }
    if (blockIdx.x == 0 && threadIdx.x < 4) g_bar[threadIdx.x] = 0u;
}

// ---------------- persistent LSTM kernel ----------------
__global__ void __launch_bounds__(NTHREADS, 1)
lstm_persist(const float* __restrict__ data, const float* __restrict__ W_ih,
             const float* __restrict__ b_ih, const float* __restrict__ b_hh,
             const float* __restrict__ W_out, const float* __restrict__ b_out,
             float* __restrict__ out, int T, int steps)
{
    extern __shared__ __align__(1024) char sm[];
    const uint32_t sb = smem_u32(sm);
    const int tid  = threadIdx.x;
    const int wid  = tid >> 5;
    const int lane = tid & 31;
    const int mb = blockIdx.x & 3;
    const int jb = blockIdx.x >> 2;
    const int m0 = mb * TILEM;
    const int j0 = jb * NH;
    const int wM = wid & 3;        // 0..3 -> 32-row slab
    const int wN = wid >> 2;       // 0..3 -> 32-col slab (8 hidden units x 4 gates)

    float* s_x    = (float*)(sm + SO_X);
    float* s_wout = (float*)(sm + SO_WOUT);
    float* s_pred = (float*)(sm + SO_PRED);

    // ---- one-time: per-thread gate weights/biases + wout, c state in regs ----
    const int hloc = wN * 8 + 2 * (lane & 3);
    float wih_r[4][2], bsum_r[4][2];
#pragma unroll
    for (int gt = 0; gt < 4; ++gt)
#pragma unroll
        for (int ej = 0; ej < 2; ++ej) {
            int j = gt * HID + j0 + hloc + ej;
            wih_r[gt][ej]  = W_ih[j];
            bsum_r[gt][ej] = b_ih[j] + b_hh[j];
        }
    if (tid < 32) s_wout[tid] = W_out[j0 + tid];
    const float bout = b_out[0];
    float c_reg[2][2][2];
#pragma unroll
    for (int a = 0; a < 2; ++a)
#pragma unroll
        for (int b = 0; b < 2; ++b)
#pragma unroll
            for (int d = 0; d < 2; ++d) c_reg[a][b][d] = 0.0f;

    const uint32_t aU = (uint32_t)((wM * 32 + (lane & 15)) * 128 + ((lane >> 4) * 8) * 2);
    const uint32_t bU = (uint32_t)((wN * 32 + (lane & 7) + ((lane >> 4) << 3)) * 128
                                   + (((lane >> 3) & 1) * 8) * 2);
    const uint32_t stg0 = sb + SO_STAGE;

    // ---- loaders: chunk = 2 subtiles of 64 K-cols (16 KB each) ----
    auto load_B = [&](int chunk, uint32_t stg) {
#pragma unroll
        for (int s = 0; s < 2; ++s) {
            const int k0 = chunk * KC + s * 64;
            const uint32_t base = stg + TO_B + s * 16384;
#pragma unroll
            for (int it = 0; it < 2; ++it) {
                int li = it * NTHREADS + tid;
                int r = li >> 3, c16 = li & 7;
                uint32_t soff = swz((uint32_t)(r * 128 + c16 * 16));
                int wrow = ((r >> 3) & 3) * HID + j0 + (r & 7) + ((r >> 5) << 3);
                size_t boff = (size_t)wrow * HID + k0 + c16 * 8;
                cp16(base + soff, g_Whi + boff);
            }
        }
    };
    auto load_A = [&](const __nv_bfloat16* hsrc, int chunk, uint32_t stg) {
#pragma unroll
        for (int s = 0; s < 2; ++s) {
            const int k0 = chunk * KC + s * 64;
            const uint32_t base = stg + TO_A + s * 16384;
#pragma unroll
            for (int it = 0; it < 2; ++it) {
                int li = it * NTHREADS + tid;
                int r = li >> 3, c16 = li & 7;
                uint32_t soff = swz((uint32_t)(r * 128 + c16 * 16));
                size_t aoff = (size_t)(m0 + r) * HID + k0 + c16 * 8;
                cp16(base + soff, hsrc + aoff);
            }
        }
    };

    const int total = T + steps - 1;   // 159 cell steps
    unsigned bar_target = 0;
    __syncthreads();

    // prefetch B chunks 0..1 for the first step
    load_B(0, stg0 + 0 * STAGE_BYTES); asm volatile("cp.async.commit_group;");
    load_B(1, stg0 + 1 * STAGE_BYTES); asm volatile("cp.async.commit_group;");

    for (int g = 0; g < total; ++g) {
        const int rbuf = (g & 1) ^ 1;
        const int wbuf = g & 1;
        const __nv_bfloat16* hsrc = g_hh[rbuf];

        // ---- prime A chunks 0..1 first (B already prefetched pre-barrier) ----
        load_A(hsrc, 0, stg0 + 0 * STAGE_BYTES); asm volatile("cp.async.commit_group;");
        load_A(hsrc, 1, stg0 + 1 * STAGE_BYTES); asm volatile("cp.async.commit_group;");

        // ---- per-step prologue: x into SMEM (+ out write for AR steps) ----
        if (tid < 128) {
            float xv;
            if (g < T) {
                xv = data[(size_t)(m0 + tid) * T + g];
            } else {
                float acc2 = 0.0f;
#pragma unroll 8
                for (int p = 0; p < 32; ++p)
                    acc2 += __ldcg(&g_parts[rbuf][p * BATCH + m0 + tid]);
                xv = acc2 + bout;
                if (jb == 0) out[(size_t)(m0 + tid) * steps + (g - T)] = xv;
            }
            s_x[tid] = xv;
        }

        float acc[2][4][4];
#pragma unroll
        for (int mt = 0; mt < 2; ++mt)
#pragma unroll
            for (int nt = 0; nt < 4; ++nt)
#pragma unroll
                for (int e = 0; e < 4; ++e) acc[mt][nt][e] = 0.0f;

#pragma unroll 1
        for (int i = 0; i < NCHUNK; ++i) {
            if (i < NCHUNK - 1) asm volatile("cp.async.wait_group 1;");
            else                asm volatile("cp.async.wait_group 0;");
            __syncthreads();
            {
                const uint32_t stg = stg0 + (i % 3) * STAGE_BYTES;
#pragma unroll
                for (int sub = 0; sub < 2; ++sub) {
                    const uint32_t stgA = stg + TO_A + sub * 16384;
                    const uint32_t stgB = stg + TO_B + sub * 16384;
#pragma unroll
                    for (int k16 = 0; k16 < 4; ++k16) {
                        const uint32_t ko = (uint32_t)k16 * 32;
                        uint32_t aHi[2][4];
#pragma unroll
                        for (int mt = 0; mt < 2; ++mt) {
                            uint32_t so = swz(aU + (uint32_t)mt * 2048 + ko);
                            ldsm4(aHi[mt], stgA + so);
                        }
                        uint32_t bH[4][2];
#pragma unroll
                        for (int half = 0; half < 2; ++half) {
                            uint32_t so = swz(bU + (uint32_t)half * 2048 + ko);
                            uint32_t t[4];
                            ldsm4(t, stgB + so);
                            bH[half*2][0] = t[0]; bH[half*2][1] = t[1];
                            bH[half*2+1][0] = t[2]; bH[half*2+1][1] = t[3];
                        }
#pragma unroll
                        for (int mt = 0; mt < 2; ++mt)
#pragma unroll
                            for (int nt = 0; nt < 4; ++nt)
                                hmma(acc[mt][nt], aHi[mt], bH[nt]);
                    }
                }
            }
            if (i + 2 < NCHUNK) {
                uint32_t stg = stg0 + ((i + 2) % 3) * STAGE_BYTES;
                load_A(hsrc, i + 2, stg);
                load_B(i + 2, stg);
                asm volatile("cp.async.commit_group;");
            }
        }

        // ---- prefetch next step's B0 into stage0 (chunk-6 stage, compute done) ----
        if (g + 1 < total) {
            load_B(0, stg0 + 0 * STAGE_BYTES); asm volatile("cp.async.commit_group;");
        }
        // stage1 held chunk 7 (last computed) -> sync before overwriting with B1
        __syncthreads();
        if (g + 1 < total) {
            load_B(1, stg0 + 1 * STAGE_BYTES); asm volatile("cp.async.commit_group;");
        }

        // ---- epilogue: register-resident cell update ----
        const float w0 = s_wout[hloc], w1 = s_wout[hloc + 1];
        const int hb = j0 + hloc;
#pragma unroll
        for (int mt = 0; mt < 2; ++mt)
#pragma unroll
            for (int eh = 0; eh < 2; ++eh) {
                const int rl = wM * 32 + mt * 16 + (lane >> 2) + eh * 8;
                const float xv = s_x[rl];
                float hn[2];
#pragma unroll
                for (int ej = 0; ej < 2; ++ej) {
                    const int e = eh * 2 + ej;
                    float gi = acc[mt][0][e] + xv * wih_r[0][ej] + bsum_r[0][ej];
                    float gf = acc[mt][1][e] + xv * wih_r[1][ej] + bsum_r[1][ej];
                    float gg = acc[mt][2][e] + xv * wih_r[2][ej] + bsum_r[2][ej];
                    float go = acc[mt][3][e] + xv * wih_r[3][ej] + bsum_r[3][ej];
                    float co = c_reg[mt][eh][ej];
                    float cn = sigf(gf) * co + sigf(gi) * tanhf_fast(gg);
                    hn[ej] = sigf(go) * tanhf_fast(cn);
                    c_reg[mt][eh][ej] = cn;
                }
                __nv_bfloat162 hv = __floats2bfloat162_rn(hn[0], hn[1]);
                *(uint32_t*)&g_hh[wbuf][(size_t)(m0 + rl) * HID + hb] =
                    *(uint32_t*)&hv;
                float p = hn[0] * w0 + hn[1] * w1;
                p += __shfl_xor_sync(0xFFFFFFFFu, p, 1);
                p += __shfl_xor_sync(0xFFFFFFFFu, p, 2);
                if ((lane & 3) == 0) s_pred[wN * 128 + rl] = p;
            }
        __syncthreads();
        if (tid < 128) {
            float p = s_pred[tid] + s_pred[128 + tid] + s_pred[256 + tid] + s_pred[384 + tid];
            g_parts[wbuf][jb * BATCH + m0 + tid] = p;
        }

        // ---- per-mb-group barrier (32 CTAs): release-red + acquire-poll ----
        bar_target += GRP_CTAS;
        __syncthreads();                    // hb: all threads' h/parts stores before tid0's release
        if (tid == 0) {
            asm volatile("red.release.gpu.global.add.u32 [%0], 1;"
                         :: "l"(&g_bar[mb]) : "memory");
            unsigned v;
            do {
                asm volatile("ld.acquire.gpu.global.u32 %0, [%1];"
                             : "=r"(v) : "l"(&g_bar[mb]) : "memory");
            } while (v < bar_target);
        }
        __syncthreads();                    // hb: release/acquire ordering to all threads
    }

    // ---- final prediction ----
    if (jb == 0 && tid < 128) {
        const int lbuf = (total - 1) & 1;
        float acc2 = 0.0f;
#pragma unroll 8
        for (int p = 0; p < 32; ++p)
            acc2 += __ldcg(&g_parts[lbuf][p * BATCH + m0 + tid]);
        out[(size_t)(m0 + tid) * steps + (steps - 1)] = acc2 + bout;
    }
}

// ---------------- launch ----------------
extern "C" void kernel_launch(void* const* d_in, const int* in_sizes, int n_in,
                              void* d_out, int out_size) {
    const float* data  = (const float*)d_in[0];  // [B, T, 1]
    const float* W_ih  = (const float*)d_in[1];  // [4H, 1]
    const float* W_hh  = (const float*)d_in[2];  // [4H, H]
    const float* b_ih  = (const float*)d_in[3];
    const float* b_hh  = (const float*)d_in[4];
    const float* W_out = (const float*)d_in[5];  // [1, H]
    const float* b_out = (const float*)d_in[6];
    float* out = (float*)d_out;                  // [B, STEPS, 1]

    int T     = in_sizes[0] / BATCH;   // 64
    int steps = out_size / BATCH;      // 96

    cudaFuncSetAttribute(lstm_persist, cudaFuncAttributeMaxDynamicSharedMemorySize, SMEM_TOTAL);

    prep_split_kernel<<<2048, 512>>>(W_hh);
    init_zero_kernel<<<512, 512>>>();

    lstm_persist<<<128, NTHREADS, SMEM_TOTAL>>>(data, W_ih, b_ih, b_hh,
                                                W_out, b_out, out, T, steps);
}